// round 11
// baseline (speedup 1.0000x reference)
#include <cuda_runtime.h>
#include <cuda_bf16.h>
#include <stdint.h>

// Problem constants
#define Bv 2
#define Nv 4
#define Dv 48
#define Hv 28
#define Wv 60
#define Cv 64
#define NXv 192
#define NYv 192
#define NZv 1
#define NYNX (NYv * NXv)
#define FULLM 0xffffffffu

// Channel-contiguous staging accumulator: [B*NY*NX][64] floats (18.9 MB).
// BSS-zeroed at module load; the transpose kernel restores it to zero at its
// tail every launch, so it is always zero when the next scatter begins.
__device__ float4 g_staging4[(size_t)Bv * NYv * NXv * (Cv / 4)];

// ---------------------------------------------------------------------------
// Per-block setup (in smem): invert intrinsics element-wise by det (matches
// LU back-substitution bit-for-bit on this matrix structure — validated
// rel_err 2.5e-7 across R1-R7), combine = R @ inv(K), stash translation.
// ---------------------------------------------------------------------------
__device__ __forceinline__ void compute_combine(
    const float* __restrict__ intr, const float* __restrict__ pose,
    int i, float* cm, float* tr) {
    const float* K = intr + i * 9;
    float a00 = K[0], a01 = K[1], a02 = K[2];
    float a10 = K[3], a11 = K[4], a12 = K[5];
    float a20 = K[6], a21 = K[7], a22 = K[8];

    float det = __fadd_rn(
        __fsub_rn(__fmul_rn(a00, __fsub_rn(__fmul_rn(a11, a22), __fmul_rn(a12, a21))),
                  __fmul_rn(a01, __fsub_rn(__fmul_rn(a10, a22), __fmul_rn(a12, a20)))),
        __fmul_rn(a02, __fsub_rn(__fmul_rn(a10, a21), __fmul_rn(a11, a20))));

    float inv[9];
    inv[0] = __fdiv_rn(__fsub_rn(__fmul_rn(a11, a22), __fmul_rn(a12, a21)), det);
    inv[1] = __fdiv_rn(__fsub_rn(__fmul_rn(a02, a21), __fmul_rn(a01, a22)), det);
    inv[2] = __fdiv_rn(__fsub_rn(__fmul_rn(a01, a12), __fmul_rn(a02, a11)), det);
    inv[3] = __fdiv_rn(__fsub_rn(__fmul_rn(a12, a20), __fmul_rn(a10, a22)), det);
    inv[4] = __fdiv_rn(__fsub_rn(__fmul_rn(a00, a22), __fmul_rn(a02, a20)), det);
    inv[5] = __fdiv_rn(__fsub_rn(__fmul_rn(a02, a10), __fmul_rn(a00, a12)), det);
    inv[6] = __fdiv_rn(__fsub_rn(__fmul_rn(a10, a21), __fmul_rn(a11, a20)), det);
    inv[7] = __fdiv_rn(__fsub_rn(__fmul_rn(a01, a20), __fmul_rn(a00, a21)), det);
    inv[8] = __fdiv_rn(__fsub_rn(__fmul_rn(a00, a11), __fmul_rn(a01, a10)), det);

    const float* P = pose + i * 16;
    #pragma unroll
    for (int r = 0; r < 3; r++) {
        float r0 = P[r * 4 + 0], r1 = P[r * 4 + 1], r2 = P[r * 4 + 2];
        #pragma unroll
        for (int c = 0; c < 3; c++) {
            cm[r * 3 + c] = __fadd_rn(
                __fadd_rn(__fmul_rn(r0, inv[0 * 3 + c]),
                          __fmul_rn(r1, inv[1 * 3 + c])),
                __fmul_rn(r2, inv[2 * 3 + c]));
        }
    }
    tr[0] = P[3];
    tr[1] = P[7];
    tr[2] = P[11];
}

__device__ __forceinline__ void red_v4(float* p, float4 a) {
    asm volatile("red.global.add.v4.f32 [%0], {%1, %2, %3, %4};" ::
                 "l"(p), "f"(a.x), "f"(a.y), "f"(a.z), "f"(a.w)
                 : "memory");
}

// Streaming float4 store: out is written once, never read. (kept from R7:
// transpose measured 11.2 -> 10.8 with it)
__device__ __forceinline__ void stcs4(float4* p, float4 a) {
    asm volatile("st.global.cs.v4.f32 [%0], {%1, %2, %3, %4};" ::
                 "l"(p), "f"(a.x), "f"(a.y), "f"(a.z), "f"(a.w) : "memory");
}

__device__ __forceinline__ float4 bfly_add4(float4 a, int m) {
    a.x += __shfl_xor_sync(FULLM, a.x, m);
    a.y += __shfl_xor_sync(FULLM, a.y, m);
    a.z += __shfl_xor_sync(FULLM, a.z, m);
    a.w += __shfl_xor_sync(FULLM, a.w, m);
    return a;
}

// ---------------------------------------------------------------------------
// Scatter: one warp = FOUR rays consecutive in h (same b,d,w), 8 lanes each,
// 8 channels per lane. Since gy depends only on w and gx only on d, the 4
// rays of a warp share one BEV cell whenever kept -> verified at runtime
// with shfl compares; on the merged path the 8 float4 accumulators are
// butterfly-reduced across ray groups and flushed by lanes 0-7 only:
// 16 REDG lane-ops per warp instead of 64, and 4x fewer same-address
// atomics at the LTS. Generic per-ray fallback preserved for arbitrary
// camera parameters. x loads use default cache policy (R7 post-mortem:
// ld.cs cost ~2us).
// ---------------------------------------------------------------------------
__global__ __launch_bounds__(256) void fp_scatter_kernel(
    const float* __restrict__ x,
    const float* __restrict__ intr,
    const float* __restrict__ pose) {
    __shared__ float s_cm[Bv * Nv][9];
    __shared__ float s_tr[Bv * Nv][3];
    int t = threadIdx.x;
    if (t < Bv * Nv) compute_combine(intr, pose, t, s_cm[t], s_tr[t]);
    __syncthreads();

    // warp -> (b, d, h4, w); ray = lane>>3 -> h = h4*4 + ray
    int gwarp = (blockIdx.x * 256 + t) >> 5;   // 0..40319 (exact grid)
    int lane = t & 31;
    int ray = lane >> 3;
    int c8 = (lane & 7) * 8;  // channel group base

    int w = gwarp % Wv;
    int tt = gwarp / Wv;
    int h4 = tt % (Hv / 4);
    tt /= (Hv / 4);
    int d = tt % Dv;
    int b = tt / Dv;
    int h = h4 * 4 + ray;

    // Frustum point (linspace with forced endpoints, matching numpy/jnp)
    float du = __fdiv_rn((float)(Wv * 8 - 1), (float)(Wv - 1));  // 479/59
    float dv = __fdiv_rn((float)(Hv * 8 - 1), (float)(Hv - 1));  // 223/27
    float u = (w == Wv - 1) ? (float)(Wv * 8 - 1) : __fmul_rn((float)w, du);
    float v = (h == Hv - 1) ? (float)(Hv * 8 - 1) : __fmul_rn((float)h, dv);
    float dd = __fadd_rn(2.0f, (float)d);
    float ud = __fmul_rn(u, dd);
    float vd = __fmul_rn(v, dd);

    int cells[Nv];
    #pragma unroll
    for (int n = 0; n < Nv; n++) {
        const float* cm = s_cm[b * Nv + n];
        const float* tr = s_tr[b * Nv + n];
        float g0 = __fadd_rn(
            __fadd_rn(__fadd_rn(__fmul_rn(cm[0], ud), __fmul_rn(cm[1], vd)),
                      __fmul_rn(cm[2], dd)),
            tr[0]);
        float g1 = __fadd_rn(
            __fadd_rn(__fadd_rn(__fmul_rn(cm[3], ud), __fmul_rn(cm[4], vd)),
                      __fmul_rn(cm[5], dd)),
            tr[1]);
        float g2 = __fadd_rn(
            __fadd_rn(__fadd_rn(__fmul_rn(cm[6], ud), __fmul_rn(cm[7], vd)),
                      __fmul_rn(cm[8], dd)),
            tr[2]);
        int gx = (int)__fadd_rn(__fmul_rn(g0, 4.0f), 96.0f);
        int gy = (int)__fadd_rn(__fmul_rn(g1, 4.0f), 96.0f);
        int gz = (int)__fdiv_rn(__fadd_rn(g2, 10.0f), 20.0f);
        bool kept = (gx >= 0) & (gx < NXv) & (gy >= 0) & (gy < NYv) &
                    (gz >= 0) & (gz < NZv);
        cells[n] = kept ? ((b * NYv + gy) * NXv + gx) : -1;
    }

    size_t xoff = (size_t)(((b * Nv * Dv + d) * Hv + h) * Wv + w) * Cv + c8;
    const size_t nstride = (size_t)Dv * Hv * Wv * Cv;

    bool alleq = (cells[0] == cells[1]) & (cells[1] == cells[2]) &
                 (cells[2] == cells[3]);
    int cell = cells[0];

    // Warp-uniform check: every lane's cell equals its xor-8 and xor-16
    // partners -> all 4 rays share one cell (or all are culled).
    bool eq8 = (__shfl_xor_sync(FULLM, cell, 8) == cell);
    bool eq16 = (__shfl_xor_sync(FULLM, cell, 16) == cell);
    bool merged = __all_sync(FULLM, alleq & eq8 & eq16);

    if (merged) {
        if (cell < 0) return;  // whole warp culled (uniform)
        // Batch all 8 independent float4 loads (MLP 8), reduce over n.
        float4 v0[Nv], v1[Nv];
        #pragma unroll
        for (int n = 0; n < Nv; n++) {
            const float4* p = (const float4*)(x + xoff + n * nstride);
            v0[n] = __ldg(p);
            v1[n] = __ldg(p + 1);
        }
        float4 a0 = v0[0], a1 = v1[0];
        #pragma unroll
        for (int n = 1; n < Nv; n++) {
            a0.x += v0[n].x; a0.y += v0[n].y; a0.z += v0[n].z; a0.w += v0[n].w;
            a1.x += v1[n].x; a1.y += v1[n].y; a1.z += v1[n].z; a1.w += v1[n].w;
        }
        // Butterfly-reduce across the 4 ray groups (lanes ^8, ^16).
        a0 = bfly_add4(a0, 8);  a0 = bfly_add4(a0, 16);
        a1 = bfly_add4(a1, 8);  a1 = bfly_add4(a1, 16);
        if (lane < 8) {
            float* p = (float*)g_staging4 + (size_t)cell * Cv + c8;
            red_v4(p, a0);
            red_v4(p + 4, a1);
        }
        return;
    }

    // Per-ray fallback (no shuffles past this point).
    if (alleq) {
        if (cell < 0) return;
        float4 v0[Nv], v1[Nv];
        #pragma unroll
        for (int n = 0; n < Nv; n++) {
            const float4* p = (const float4*)(x + xoff + n * nstride);
            v0[n] = __ldg(p);
            v1[n] = __ldg(p + 1);
        }
        float4 a0 = v0[0], a1 = v1[0];
        #pragma unroll
        for (int n = 1; n < Nv; n++) {
            a0.x += v0[n].x; a0.y += v0[n].y; a0.z += v0[n].z; a0.w += v0[n].w;
            a1.x += v1[n].x; a1.y += v1[n].y; a1.z += v1[n].z; a1.w += v1[n].w;
        }
        float* p = (float*)g_staging4 + (size_t)cell * Cv + c8;
        red_v4(p, a0);
        red_v4(p + 4, a1);
    } else {
        float4 a0 = make_float4(0, 0, 0, 0), a1 = make_float4(0, 0, 0, 0);
        int cur = -1;
        #pragma unroll
        for (int n = 0; n < Nv; n++) {
            if (cells[n] != cur) {
                if (cur >= 0) {
                    float* p = (float*)g_staging4 + (size_t)cur * Cv + c8;
                    red_v4(p, a0);
                    red_v4(p + 4, a1);
                }
                a0 = make_float4(0, 0, 0, 0);
                a1 = make_float4(0, 0, 0, 0);
                cur = cells[n];
            }
            if (cells[n] >= 0) {
                const float4* p = (const float4*)(x + xoff + n * nstride);
                float4 w0 = __ldg(p), w1 = __ldg(p + 1);
                a0.x += w0.x; a0.y += w0.y; a0.z += w0.z; a0.w += w0.w;
                a1.x += w1.x; a1.y += w1.y; a1.z += w1.z; a1.w += w1.w;
            }
        }
        if (cur >= 0) {
            float* p = (float*)g_staging4 + (size_t)cur * Cv + c8;
            red_v4(p, a0);
            red_v4(p + 4, a1);
        }
    }
}

// ---------------------------------------------------------------------------
// Transpose staging (B, NY, NX, C) -> out (B, C, NY, NX), float4 both ways.
// R4 structure + stcs stores (measured best: 10.8 us).
// Staging re-zero deferred to the kernel tail (R4 lesson: same-address
// STG-after-LDG parks behind the load in L1tex and stalls the LSU).
// ---------------------------------------------------------------------------
__global__ __launch_bounds__(256) void fp_transpose_kernel(float* __restrict__ out) {
    __shared__ float tile[32 * 65];
    int blk = blockIdx.x;
    int gxt = blk % (NXv / 32);
    int t1 = blk / (NXv / 32);
    int gy = t1 % NYv;
    int b = t1 / NYv;
    int gx0 = gxt * 32;
    int t = threadIdx.x;

    float4* src = g_staging4 + ((size_t)(b * NYv + gy) * NXv + gx0) * (Cv / 4);

    #pragma unroll
    for (int it = 0; it < 2; it++) {
        int uu = t + it * 256;       // 0..511 float4 units
        int gx = uu >> 4;
        int c4 = (uu & 15) * 4;
        float4 vv = src[uu];
        tile[gx * 65 + c4 + 0] = vv.x;
        tile[gx * 65 + c4 + 1] = vv.y;
        tile[gx * 65 + c4 + 2] = vv.z;
        tile[gx * 65 + c4 + 3] = vv.w;
    }
    __syncthreads();

    #pragma unroll
    for (int it = 0; it < 2; it++) {
        int uu = t + it * 256;       // 0..511 output float4 units
        int gx4 = uu & 7;            // 4-wide gx group
        int c = uu >> 3;             // 0..63
        float4 o;
        o.x = tile[(gx4 * 4 + 0) * 65 + c];
        o.y = tile[(gx4 * 4 + 1) * 65 + c];
        o.z = tile[(gx4 * 4 + 2) * 65 + c];
        o.w = tile[(gx4 * 4 + 3) * 65 + c];
        float4* dst = (float4*)(out + (size_t)(b * Cv + c) * NYNX +
                                gy * NXv + gx0 + gx4 * 4);
        stcs4(dst, o);
    }

    // Tail: restore staging to zero for the next graph replay (fire-and-
    // forget; matching loads completed long ago). Default cache policy —
    // staging should STAY L2-resident for the next scatter's atomics.
    const float4 z4 = make_float4(0.f, 0.f, 0.f, 0.f);
    src[t] = z4;
    src[t + 256] = z4;
}

extern "C" void kernel_launch(void* const* d_in, const int* in_sizes, int n_in,
                              void* d_out, int out_size) {
    const float* x = (const float*)d_in[0];
    const float* intr = (const float*)d_in[1];
    const float* pose = (const float*)d_in[2];
    float* out = (float*)d_out;

    // 1) scatter (4 h-consecutive rays per warp, warp-merged vector atomics)
    const int W = Bv * Dv * (Hv / 4) * Wv;   // 40320 warps
    int blocks = W / 8;                       // 5040 blocks of 8 warps
    fp_scatter_kernel<<<blocks, 256>>>(x, intr, pose);

    // 2) transpose staging -> out; re-zeroes staging at its tail
    int tblocks = Bv * NYv * (NXv / 32);      // 2304
    fp_transpose_kernel<<<tblocks, 256>>>(out);
}

// round 12
// speedup vs baseline: 1.1404x; 1.1404x over previous
#include <cuda_runtime.h>
#include <cuda_bf16.h>
#include <stdint.h>

// Problem constants
#define Bv 2
#define Nv 4
#define Dv 48
#define Hv 28
#define Wv 60
#define Cv 64
#define NXv 192
#define NYv 192
#define NZv 1
#define NYNX (NYv * NXv)
#define FULLM 0xffffffffu
#define HN (Hv * Nv)   // 112 (h,n) slices per (b,d,w) column

// ---------------------------------------------------------------------------
// Intrinsics inversion + combine = R @ inv(K): element-wise division by det
// matches LU back-substitution bit-for-bit on this matrix structure
// (validated rel_err ~2.5e-7 across R1-R8). Same op order as the reference.
// ---------------------------------------------------------------------------
__device__ __forceinline__ void compute_combine(
    const float* __restrict__ intr, const float* __restrict__ pose,
    int i, float* cm, float* tr) {
    const float* K = intr + i * 9;
    float a00 = K[0], a01 = K[1], a02 = K[2];
    float a10 = K[3], a11 = K[4], a12 = K[5];
    float a20 = K[6], a21 = K[7], a22 = K[8];

    float det = __fadd_rn(
        __fsub_rn(__fmul_rn(a00, __fsub_rn(__fmul_rn(a11, a22), __fmul_rn(a12, a21))),
                  __fmul_rn(a01, __fsub_rn(__fmul_rn(a10, a22), __fmul_rn(a12, a20)))),
        __fmul_rn(a02, __fsub_rn(__fmul_rn(a10, a21), __fmul_rn(a11, a20))));

    float inv[9];
    inv[0] = __fdiv_rn(__fsub_rn(__fmul_rn(a11, a22), __fmul_rn(a12, a21)), det);
    inv[1] = __fdiv_rn(__fsub_rn(__fmul_rn(a02, a21), __fmul_rn(a01, a22)), det);
    inv[2] = __fdiv_rn(__fsub_rn(__fmul_rn(a01, a12), __fmul_rn(a02, a11)), det);
    inv[3] = __fdiv_rn(__fsub_rn(__fmul_rn(a12, a20), __fmul_rn(a10, a22)), det);
    inv[4] = __fdiv_rn(__fsub_rn(__fmul_rn(a00, a22), __fmul_rn(a02, a20)), det);
    inv[5] = __fdiv_rn(__fsub_rn(__fmul_rn(a02, a10), __fmul_rn(a00, a12)), det);
    inv[6] = __fdiv_rn(__fsub_rn(__fmul_rn(a10, a21), __fmul_rn(a11, a20)), det);
    inv[7] = __fdiv_rn(__fsub_rn(__fmul_rn(a01, a20), __fmul_rn(a00, a21)), det);
    inv[8] = __fdiv_rn(__fsub_rn(__fmul_rn(a00, a11), __fmul_rn(a01, a10)), det);

    const float* P = pose + i * 16;
    #pragma unroll
    for (int r = 0; r < 3; r++) {
        float r0 = P[r * 4 + 0], r1 = P[r * 4 + 1], r2 = P[r * 4 + 2];
        #pragma unroll
        for (int c = 0; c < 3; c++) {
            cm[r * 3 + c] = __fadd_rn(
                __fadd_rn(__fmul_rn(r0, inv[0 * 3 + c]),
                          __fmul_rn(r1, inv[1 * 3 + c])),
                __fmul_rn(r2, inv[2 * 3 + c]));
        }
    }
    tr[0] = P[3];
    tr[1] = P[7];
    tr[2] = P[11];
}

// ---------------------------------------------------------------------------
// Zero the output (harness poisons it to 0xAA). Pure contiguous STG.128.
// ---------------------------------------------------------------------------
__global__ __launch_bounds__(256) void fp_zero_out(float4* __restrict__ out4, int n4) {
    int idx = blockIdx.x * 256 + threadIdx.x;
    int stride = gridDim.x * 256;
    const float4 z = make_float4(0.f, 0.f, 0.f, 0.f);
    #pragma unroll 4
    for (int i = idx; i < n4; i += stride) out4[i] = z;
}

// ---------------------------------------------------------------------------
// Direct scatter: one block = one (b, d, w) column = 112 (h,n) slices of 64
// channels. geom_x/geom_y have no v(h)-dependence and the cameras share
// pose/intrinsics, so all kept slices of a column target ONE BEV cell —
// verified at runtime (ballot compaction + __syncthreads_and), with a
// generic per-slice fallback for arbitrary inputs.
// Fast path: 4 thread-groups x 64 channels accumulate the kept list with
// coalesced 128B loads, smem tree-reduce, then 64 scalar atomicAdds
// straight into the final (B, C, NY, NX) output. No staging, no transpose.
// Culled columns (majority) exit after the any-kept ballot (~300 cyc).
// ---------------------------------------------------------------------------
__global__ __launch_bounds__(256) void fp_scatter_direct(
    const float* __restrict__ x,
    const float* __restrict__ intr,
    const float* __restrict__ pose,
    float* __restrict__ out) {
    __shared__ float s_cm[Nv][9];
    __shared__ float s_tr[Nv][3];
    __shared__ int s_cell[HN];      // bev index (gy*NX+gx) or -1, per (h,n)
    __shared__ int s_xoff[HN];      // x element offset of slice (h,n)
    __shared__ int s_lcell[HN];     // compacted kept cells
    __shared__ int s_loff[HN];      // compacted kept x offsets
    __shared__ unsigned s_mask[4];  // per-warp kept ballots (warps 0-3)
    __shared__ float s_part[4][Cv]; // partial sums for the tree reduce

    int t = threadIdx.x;
    int blk = blockIdx.x;
    int w = blk % Wv;
    int t1 = blk / Wv;
    int d = t1 % Dv;
    int b = t1 / Dv;

    if (t < Nv) compute_combine(intr, pose, b * Nv + t, s_cm[t], s_tr[t]);
    __syncthreads();

    // Geometry for the 112 (h,n) slices (threads 0..111).
    bool kept = false;
    int cellv = -1, xoffv = 0;
    if (t < HN) {
        int n = t & 3;
        int h = t >> 2;

        // Frustum point (linspace with forced endpoints, matching numpy/jnp)
        float du = __fdiv_rn((float)(Wv * 8 - 1), (float)(Wv - 1));  // 479/59
        float dv = __fdiv_rn((float)(Hv * 8 - 1), (float)(Hv - 1));  // 223/27
        float u = (w == Wv - 1) ? (float)(Wv * 8 - 1) : __fmul_rn((float)w, du);
        float v = (h == Hv - 1) ? (float)(Hv * 8 - 1) : __fmul_rn((float)h, dv);
        float dd = __fadd_rn(2.0f, (float)d);
        float ud = __fmul_rn(u, dd);
        float vd = __fmul_rn(v, dd);

        const float* cm = s_cm[n];
        const float* tr = s_tr[n];
        float g0 = __fadd_rn(
            __fadd_rn(__fadd_rn(__fmul_rn(cm[0], ud), __fmul_rn(cm[1], vd)),
                      __fmul_rn(cm[2], dd)),
            tr[0]);
        float g1 = __fadd_rn(
            __fadd_rn(__fadd_rn(__fmul_rn(cm[3], ud), __fmul_rn(cm[4], vd)),
                      __fmul_rn(cm[5], dd)),
            tr[1]);
        float g2 = __fadd_rn(
            __fadd_rn(__fadd_rn(__fmul_rn(cm[6], ud), __fmul_rn(cm[7], vd)),
                      __fmul_rn(cm[8], dd)),
            tr[2]);
        int gx = (int)__fadd_rn(__fmul_rn(g0, 4.0f), 96.0f);
        int gy = (int)__fadd_rn(__fmul_rn(g1, 4.0f), 96.0f);
        int gz = (int)__fdiv_rn(__fadd_rn(g2, 10.0f), 20.0f);
        kept = (gx >= 0) & (gx < NXv) & (gy >= 0) & (gy < NYv) &
               (gz >= 0) & (gz < NZv);
        cellv = kept ? (gy * NXv + gx) : -1;
        xoffv = ((((b * Nv + n) * Dv + d) * Hv + h) * Wv + w) * Cv;
        s_cell[t] = cellv;
        s_xoff[t] = xoffv;
    }
    int wu = t >> 5;
    if (wu < 4) {
        unsigned m = __ballot_sync(FULLM, kept);
        if ((t & 31) == 0) s_mask[wu] = m;
    }
    __syncthreads();

    // Warp-prefix compaction offsets; early out if nothing kept.
    unsigned m0 = s_mask[0], m1 = s_mask[1], m2 = s_mask[2], m3 = s_mask[3];
    int base1 = __popc(m0);
    int base2 = base1 + __popc(m1);
    int base3 = base2 + __popc(m2);
    int K = base3 + __popc(m3);
    if (K == 0) return;

    if (t < HN && kept) {
        int lane = t & 31;
        unsigned mm = s_mask[wu];
        int basew = (wu == 0) ? 0 : (wu == 1) ? base1 : (wu == 2) ? base2 : base3;
        int pos = basew + __popc(mm & ((1u << lane) - 1u));
        s_lcell[pos] = cellv;
        s_loff[pos] = xoffv;
    }
    __syncthreads();

    int ref = s_lcell[0];
    int ok = (t < HN) ? ((s_cell[t] < 0) | (s_cell[t] == ref)) : 1;
    int alleq = __syncthreads_and(ok);

    if (alleq) {
        // Fast path: all kept slices share one cell.
        int c = t & 63;
        int p = t >> 6;  // 0..3
        float acc = 0.f;
        #pragma unroll 4
        for (int kk = p; kk < K; kk += 4) {
            acc += __ldg(x + s_loff[kk] + c);
        }
        s_part[p][c] = acc;
        __syncthreads();
        if (t < Cv) {
            float sum = ((s_part[0][t] + s_part[1][t]) +
                         (s_part[2][t] + s_part[3][t]));
            atomicAdd(out + (size_t)(b * Cv + t) * NYNX + ref, sum);
        }
    } else {
        // Generic fallback: per-slice atomic add (correct for any inputs).
        for (int kk = 0; kk < K; kk++) {
            int off = s_loff[kk];
            int cell = s_lcell[kk];
            if (t < Cv) {
                atomicAdd(out + (size_t)(b * Cv + t) * NYNX + cell,
                          __ldg(x + off + t));
            }
        }
    }
}

extern "C" void kernel_launch(void* const* d_in, const int* in_sizes, int n_in,
                              void* d_out, int out_size) {
    const float* x = (const float*)d_in[0];
    const float* intr = (const float*)d_in[1];
    const float* pose = (const float*)d_in[2];
    float* out = (float*)d_out;

    // 1) zero the output (poisoned by harness)
    int n4 = out_size / 4;                   // 1,179,648 float4
    fp_zero_out<<<1152, 256>>>((float4*)out, n4);

    // 2) direct scatter: one block per (b, d, w) column, reduce in smem,
    //    flush straight into the final layout
    int blocks = Bv * Dv * Wv;               // 5760
    fp_scatter_direct<<<blocks, 256>>>(x, intr, pose, out);
}

// round 13
// speedup vs baseline: 1.3216x; 1.1589x over previous
#include <cuda_runtime.h>
#include <cuda_bf16.h>
#include <stdint.h>

// Problem constants
#define Bv 2
#define Nv 4
#define Dv 48
#define Hv 28
#define Wv 60
#define Cv 64
#define NXv 192
#define NYv 192
#define NZv 1
#define NYNX (NYv * NXv)
#define FULLM 0xffffffffu
#define HN (Hv * Nv)   // 112 (h,n) slices per (b,d,w) column

// ---------------------------------------------------------------------------
// Intrinsics inversion + combine = R @ inv(K): element-wise division by det
// matches LU back-substitution bit-for-bit on this matrix structure
// (validated rel_err ~2.4e-7 across R1-R9). Same op order as the reference.
// ---------------------------------------------------------------------------
__device__ __forceinline__ void compute_combine(
    const float* __restrict__ intr, const float* __restrict__ pose,
    int i, float* cm, float* tr) {
    const float* K = intr + i * 9;
    float a00 = K[0], a01 = K[1], a02 = K[2];
    float a10 = K[3], a11 = K[4], a12 = K[5];
    float a20 = K[6], a21 = K[7], a22 = K[8];

    float det = __fadd_rn(
        __fsub_rn(__fmul_rn(a00, __fsub_rn(__fmul_rn(a11, a22), __fmul_rn(a12, a21))),
                  __fmul_rn(a01, __fsub_rn(__fmul_rn(a10, a22), __fmul_rn(a12, a20)))),
        __fmul_rn(a02, __fsub_rn(__fmul_rn(a10, a21), __fmul_rn(a11, a20))));

    float inv[9];
    inv[0] = __fdiv_rn(__fsub_rn(__fmul_rn(a11, a22), __fmul_rn(a12, a21)), det);
    inv[1] = __fdiv_rn(__fsub_rn(__fmul_rn(a02, a21), __fmul_rn(a01, a22)), det);
    inv[2] = __fdiv_rn(__fsub_rn(__fmul_rn(a01, a12), __fmul_rn(a02, a11)), det);
    inv[3] = __fdiv_rn(__fsub_rn(__fmul_rn(a12, a20), __fmul_rn(a10, a22)), det);
    inv[4] = __fdiv_rn(__fsub_rn(__fmul_rn(a00, a22), __fmul_rn(a02, a20)), det);
    inv[5] = __fdiv_rn(__fsub_rn(__fmul_rn(a02, a10), __fmul_rn(a00, a12)), det);
    inv[6] = __fdiv_rn(__fsub_rn(__fmul_rn(a10, a21), __fmul_rn(a11, a20)), det);
    inv[7] = __fdiv_rn(__fsub_rn(__fmul_rn(a01, a20), __fmul_rn(a00, a21)), det);
    inv[8] = __fdiv_rn(__fsub_rn(__fmul_rn(a00, a11), __fmul_rn(a01, a10)), det);

    const float* P = pose + i * 16;
    #pragma unroll
    for (int r = 0; r < 3; r++) {
        float r0 = P[r * 4 + 0], r1 = P[r * 4 + 1], r2 = P[r * 4 + 2];
        #pragma unroll
        for (int c = 0; c < 3; c++) {
            cm[r * 3 + c] = __fadd_rn(
                __fadd_rn(__fmul_rn(r0, inv[0 * 3 + c]),
                          __fmul_rn(r1, inv[1 * 3 + c])),
                __fmul_rn(r2, inv[2 * 3 + c]));
        }
    }
    tr[0] = P[3];
    tr[1] = P[7];
    tr[2] = P[11];
}

// ---------------------------------------------------------------------------
// Zero the output (harness poisons it to 0xAA). Pure contiguous STG.128.
// ---------------------------------------------------------------------------
__global__ __launch_bounds__(256) void fp_zero_out(float4* __restrict__ out4, int n4) {
    int idx = blockIdx.x * 256 + threadIdx.x;
    int stride = gridDim.x * 256;
    const float4 z = make_float4(0.f, 0.f, 0.f, 0.f);
    #pragma unroll 4
    for (int i = idx; i < n4; i += stride) out4[i] = z;
}

// ---------------------------------------------------------------------------
// Direct scatter: one block = one (b, d, w) column = 112 (h,n) slices of 64
// channels. geom_x/geom_y have no v(h)-dependence and the cameras share
// pose/intrinsics, so all kept slices of a column target ONE BEV cell —
// verified at runtime (ballot compaction + __syncthreads_and), with a
// generic per-slice fallback for arbitrary inputs.
// Fast path (R10: vectorized): 16 slice-groups x 16 float4-channel-groups;
// each thread LDG.128s one float4 per kept slice (512B per warp-instruction,
// 4x R9), unroll-4 for MLP, smem tree-reduce over the 16 groups, then 64
// scalar atomicAdds straight into the final (B, C, NY, NX) output.
// Culled columns (majority) exit right after the ballot.
// ---------------------------------------------------------------------------
__global__ __launch_bounds__(256) void fp_scatter_direct(
    const float* __restrict__ x,
    const float* __restrict__ intr,
    const float* __restrict__ pose,
    float* __restrict__ out) {
    __shared__ float s_cm[Nv][9];
    __shared__ float s_tr[Nv][3];
    __shared__ int s_cell[HN];      // bev index (gy*NX+gx) or -1, per (h,n)
    __shared__ int s_xoff[HN];      // x element offset of slice (h,n)
    __shared__ int s_lcell[HN];     // compacted kept cells
    __shared__ int s_loff[HN];      // compacted kept x offsets
    __shared__ unsigned s_mask[4];  // per-warp kept ballots (warps 0-3)
    __shared__ float s_part[16][Cv]; // partial sums (16 slice-groups x 64 c)

    int t = threadIdx.x;
    int blk = blockIdx.x;
    int w = blk % Wv;
    int t1 = blk / Wv;
    int d = t1 % Dv;
    int b = t1 / Dv;

    if (t < Nv) compute_combine(intr, pose, b * Nv + t, s_cm[t], s_tr[t]);
    __syncthreads();

    // Geometry for the 112 (h,n) slices (threads 0..111).
    bool kept = false;
    int cellv = -1, xoffv = 0;
    if (t < HN) {
        int n = t & 3;
        int h = t >> 2;

        // Frustum point (linspace with forced endpoints, matching numpy/jnp)
        float du = __fdiv_rn((float)(Wv * 8 - 1), (float)(Wv - 1));  // 479/59
        float dv = __fdiv_rn((float)(Hv * 8 - 1), (float)(Hv - 1));  // 223/27
        float u = (w == Wv - 1) ? (float)(Wv * 8 - 1) : __fmul_rn((float)w, du);
        float v = (h == Hv - 1) ? (float)(Hv * 8 - 1) : __fmul_rn((float)h, dv);
        float dd = __fadd_rn(2.0f, (float)d);
        float ud = __fmul_rn(u, dd);
        float vd = __fmul_rn(v, dd);

        const float* cm = s_cm[n];
        const float* tr = s_tr[n];
        float g0 = __fadd_rn(
            __fadd_rn(__fadd_rn(__fmul_rn(cm[0], ud), __fmul_rn(cm[1], vd)),
                      __fmul_rn(cm[2], dd)),
            tr[0]);
        float g1 = __fadd_rn(
            __fadd_rn(__fadd_rn(__fmul_rn(cm[3], ud), __fmul_rn(cm[4], vd)),
                      __fmul_rn(cm[5], dd)),
            tr[1]);
        float g2 = __fadd_rn(
            __fadd_rn(__fadd_rn(__fmul_rn(cm[6], ud), __fmul_rn(cm[7], vd)),
                      __fmul_rn(cm[8], dd)),
            tr[2]);
        int gx = (int)__fadd_rn(__fmul_rn(g0, 4.0f), 96.0f);
        int gy = (int)__fadd_rn(__fmul_rn(g1, 4.0f), 96.0f);
        int gz = (int)__fdiv_rn(__fadd_rn(g2, 10.0f), 20.0f);
        kept = (gx >= 0) & (gx < NXv) & (gy >= 0) & (gy < NYv) &
               (gz >= 0) & (gz < NZv);
        cellv = kept ? (gy * NXv + gx) : -1;
        xoffv = ((((b * Nv + n) * Dv + d) * Hv + h) * Wv + w) * Cv;
        s_cell[t] = cellv;
        s_xoff[t] = xoffv;
    }
    int wu = t >> 5;
    if (wu < 4) {
        unsigned m = __ballot_sync(FULLM, kept);
        if ((t & 31) == 0) s_mask[wu] = m;
    }
    __syncthreads();

    // Warp-prefix compaction offsets; early out if nothing kept.
    unsigned m0 = s_mask[0], m1 = s_mask[1], m2 = s_mask[2], m3 = s_mask[3];
    int base1 = __popc(m0);
    int base2 = base1 + __popc(m1);
    int base3 = base2 + __popc(m2);
    int K = base3 + __popc(m3);
    if (K == 0) return;

    if (t < HN && kept) {
        int lane = t & 31;
        unsigned mm = s_mask[wu];
        int basew = (wu == 0) ? 0 : (wu == 1) ? base1 : (wu == 2) ? base2 : base3;
        int pos = basew + __popc(mm & ((1u << lane) - 1u));
        s_lcell[pos] = cellv;
        s_loff[pos] = xoffv;
    }
    __syncthreads();

    int ref = s_lcell[0];
    int ok = (t < HN) ? ((s_cell[t] < 0) | (s_cell[t] == ref)) : 1;
    int alleq = __syncthreads_and(ok);

    if (alleq) {
        // Fast path: all kept slices share one cell. Vectorized reduce:
        // c4 = float4 channel group (0..15), p = slice group (0..15).
        int c4 = t & 15;
        int p = t >> 4;
        float4 acc = make_float4(0.f, 0.f, 0.f, 0.f);
        #pragma unroll 4
        for (int kk = p; kk < K; kk += 16) {
            float4 vv = __ldg((const float4*)(x + s_loff[kk]) + c4);
            acc.x += vv.x; acc.y += vv.y; acc.z += vv.z; acc.w += vv.w;
        }
        float* dstp = &s_part[p][c4 * 4];
        dstp[0] = acc.x; dstp[1] = acc.y; dstp[2] = acc.z; dstp[3] = acc.w;
        __syncthreads();
        if (t < Cv) {
            float sum = 0.f;
            #pragma unroll
            for (int p2 = 0; p2 < 16; p2++) sum += s_part[p2][t];
            atomicAdd(out + (size_t)(b * Cv + t) * NYNX + ref, sum);
        }
    } else {
        // Generic fallback: per-slice atomic add (correct for any inputs).
        for (int kk = 0; kk < K; kk++) {
            int off = s_loff[kk];
            int cell = s_lcell[kk];
            if (t < Cv) {
                atomicAdd(out + (size_t)(b * Cv + t) * NYNX + cell,
                          __ldg(x + off + t));
            }
        }
    }
}

extern "C" void kernel_launch(void* const* d_in, const int* in_sizes, int n_in,
                              void* d_out, int out_size) {
    const float* x = (const float*)d_in[0];
    const float* intr = (const float*)d_in[1];
    const float* pose = (const float*)d_in[2];
    float* out = (float*)d_out;

    // 1) zero the output (poisoned by harness)
    int n4 = out_size / 4;                   // 1,179,648 float4
    fp_zero_out<<<1152, 256>>>((float4*)out, n4);

    // 2) direct scatter: one block per (b, d, w) column, vectorized smem
    //    reduce, flush straight into the final layout
    int blocks = Bv * Dv * Wv;               // 5760
    fp_scatter_direct<<<blocks, 256>>>(x, intr, pose, out);
}

// round 14
// speedup vs baseline: 1.7209x; 1.3021x over previous
#include <cuda_runtime.h>
#include <cuda_bf16.h>
#include <stdint.h>

// Problem constants
#define Bv 2
#define Nv 4
#define Dv 48
#define Hv 28
#define Wv 60
#define Cv 64
#define NXv 192
#define NYv 192
#define NZv 1
#define NYNX (NYv * NXv)
#define FULLM 0xffffffffu
#define HN (Hv * Nv)   // 112 (h,n) slices per (b,d,w) column

// Precomputed per-(b,n) combine = R @ inv(K) and translation (written once
// by the zero/setup kernel, read by every scatter block).
__device__ float g_cmd[Bv * Nv][9];
__device__ float g_trd[Bv * Nv][3];

// ---------------------------------------------------------------------------
// Intrinsics inversion + combine = R @ inv(K): element-wise division by det
// matches LU back-substitution bit-for-bit on this matrix structure
// (validated rel_err ~2.4e-7 across R1-R10). Same op order as the reference.
// ---------------------------------------------------------------------------
__device__ __forceinline__ void compute_combine(
    const float* __restrict__ intr, const float* __restrict__ pose,
    int i, float* cm, float* tr) {
    const float* K = intr + i * 9;
    float a00 = K[0], a01 = K[1], a02 = K[2];
    float a10 = K[3], a11 = K[4], a12 = K[5];
    float a20 = K[6], a21 = K[7], a22 = K[8];

    float det = __fadd_rn(
        __fsub_rn(__fmul_rn(a00, __fsub_rn(__fmul_rn(a11, a22), __fmul_rn(a12, a21))),
                  __fmul_rn(a01, __fsub_rn(__fmul_rn(a10, a22), __fmul_rn(a12, a20)))),
        __fmul_rn(a02, __fsub_rn(__fmul_rn(a10, a21), __fmul_rn(a11, a20))));

    float inv[9];
    inv[0] = __fdiv_rn(__fsub_rn(__fmul_rn(a11, a22), __fmul_rn(a12, a21)), det);
    inv[1] = __fdiv_rn(__fsub_rn(__fmul_rn(a02, a21), __fmul_rn(a01, a22)), det);
    inv[2] = __fdiv_rn(__fsub_rn(__fmul_rn(a01, a12), __fmul_rn(a02, a11)), det);
    inv[3] = __fdiv_rn(__fsub_rn(__fmul_rn(a12, a20), __fmul_rn(a10, a22)), det);
    inv[4] = __fdiv_rn(__fsub_rn(__fmul_rn(a00, a22), __fmul_rn(a02, a20)), det);
    inv[5] = __fdiv_rn(__fsub_rn(__fmul_rn(a02, a10), __fmul_rn(a00, a12)), det);
    inv[6] = __fdiv_rn(__fsub_rn(__fmul_rn(a10, a21), __fmul_rn(a11, a20)), det);
    inv[7] = __fdiv_rn(__fsub_rn(__fmul_rn(a01, a20), __fmul_rn(a00, a21)), det);
    inv[8] = __fdiv_rn(__fsub_rn(__fmul_rn(a00, a11), __fmul_rn(a01, a10)), det);

    const float* P = pose + i * 16;
    #pragma unroll
    for (int r = 0; r < 3; r++) {
        float r0 = P[r * 4 + 0], r1 = P[r * 4 + 1], r2 = P[r * 4 + 2];
        #pragma unroll
        for (int c = 0; c < 3; c++) {
            cm[r * 3 + c] = __fadd_rn(
                __fadd_rn(__fmul_rn(r0, inv[0 * 3 + c]),
                          __fmul_rn(r1, inv[1 * 3 + c])),
                __fmul_rn(r2, inv[2 * 3 + c]));
        }
    }
    tr[0] = P[3];
    tr[1] = P[7];
    tr[2] = P[11];
}

// ---------------------------------------------------------------------------
// Zero the output (harness poisons it to 0xAA) AND hoist the matrix setup:
// block 0 computes the 8 combine matrices ONCE into device globals. The
// scatter (launched after, stream-ordered) just loads 48 floats per block —
// no more 9 fp-division chains behind every block's barrier.
// ---------------------------------------------------------------------------
__global__ __launch_bounds__(256) void fp_zero_setup(
    float4* __restrict__ out4, int n4,
    const float* __restrict__ intr, const float* __restrict__ pose) {
    if (blockIdx.x == 0 && threadIdx.x < Bv * Nv) {
        int i = threadIdx.x;
        compute_combine(intr, pose, i, g_cmd[i], g_trd[i]);
    }
    int idx = blockIdx.x * 256 + threadIdx.x;
    int stride = gridDim.x * 256;
    const float4 z = make_float4(0.f, 0.f, 0.f, 0.f);
    #pragma unroll 4
    for (int i = idx; i < n4; i += stride) out4[i] = z;
}

// ---------------------------------------------------------------------------
// Direct scatter: one block = one (b, d, w) column = 112 (h,n) slices of 64
// channels. geom_x/geom_y have no v(h)-dependence and the cameras share
// pose/intrinsics, so all kept slices of a column target ONE BEV cell —
// verified at runtime (ballot compaction + __syncthreads_and), with a
// generic per-slice fallback for arbitrary inputs.
// Fast path: 16 slice-groups x 16 float4-channel-groups; offsets prefetched
// and the <=7 LDG.128 issued back-to-back (MLP 7), smem tree-reduce, then
// 64 scalar atomicAdds straight into the final (B, C, NY, NX) output.
// ---------------------------------------------------------------------------
__global__ __launch_bounds__(256) void fp_scatter_direct(
    const float* __restrict__ x,
    float* __restrict__ out) {
    __shared__ float s_cm[Nv][9];
    __shared__ float s_tr[Nv][3];
    __shared__ int s_cell[HN];      // bev index (gy*NX+gx) or -1, per (h,n)
    __shared__ int s_xoff[HN];      // x element offset of slice (h,n)
    __shared__ int s_lcell[HN];     // compacted kept cells
    __shared__ int s_loff[HN];      // compacted kept x offsets
    __shared__ unsigned s_mask[4];  // per-warp kept ballots (warps 0-3)
    __shared__ float s_part[16][Cv]; // partial sums (16 slice-groups x 64 c)

    int t = threadIdx.x;
    int blk = blockIdx.x;
    int w = blk % Wv;
    int t1 = blk / Wv;
    int d = t1 % Dv;
    int b = t1 / Dv;

    // Copy this batch's 4 matrices from device globals (one coalesced load).
    if (t < Nv * 9)  ((float*)s_cm)[t] = ((const float*)g_cmd)[b * Nv * 9 + t];
    if (t >= 64 && t < 64 + Nv * 3)
        ((float*)s_tr)[t - 64] = ((const float*)g_trd)[b * Nv * 3 + (t - 64)];
    __syncthreads();

    // Geometry for the 112 (h,n) slices (threads 0..111).
    bool kept = false;
    int cellv = -1, xoffv = 0;
    if (t < HN) {
        int n = t & 3;
        int h = t >> 2;

        // Frustum point (linspace with forced endpoints, matching numpy/jnp)
        float du = __fdiv_rn((float)(Wv * 8 - 1), (float)(Wv - 1));  // 479/59
        float dv = __fdiv_rn((float)(Hv * 8 - 1), (float)(Hv - 1));  // 223/27
        float u = (w == Wv - 1) ? (float)(Wv * 8 - 1) : __fmul_rn((float)w, du);
        float v = (h == Hv - 1) ? (float)(Hv * 8 - 1) : __fmul_rn((float)h, dv);
        float dd = __fadd_rn(2.0f, (float)d);
        float ud = __fmul_rn(u, dd);
        float vd = __fmul_rn(v, dd);

        const float* cm = s_cm[n];
        const float* tr = s_tr[n];
        float g0 = __fadd_rn(
            __fadd_rn(__fadd_rn(__fmul_rn(cm[0], ud), __fmul_rn(cm[1], vd)),
                      __fmul_rn(cm[2], dd)),
            tr[0]);
        float g1 = __fadd_rn(
            __fadd_rn(__fadd_rn(__fmul_rn(cm[3], ud), __fmul_rn(cm[4], vd)),
                      __fmul_rn(cm[5], dd)),
            tr[1]);
        float g2 = __fadd_rn(
            __fadd_rn(__fadd_rn(__fmul_rn(cm[6], ud), __fmul_rn(cm[7], vd)),
                      __fmul_rn(cm[8], dd)),
            tr[2]);
        int gx = (int)__fadd_rn(__fmul_rn(g0, 4.0f), 96.0f);
        int gy = (int)__fadd_rn(__fmul_rn(g1, 4.0f), 96.0f);
        int gz = (int)__fdiv_rn(__fadd_rn(g2, 10.0f), 20.0f);
        kept = (gx >= 0) & (gx < NXv) & (gy >= 0) & (gy < NYv) &
               (gz >= 0) & (gz < NZv);
        cellv = kept ? (gy * NXv + gx) : -1;
        xoffv = ((((b * Nv + n) * Dv + d) * Hv + h) * Wv + w) * Cv;
        s_cell[t] = cellv;
        s_xoff[t] = xoffv;
    }
    int wu = t >> 5;
    if (wu < 4) {
        unsigned m = __ballot_sync(FULLM, kept);
        if ((t & 31) == 0) s_mask[wu] = m;
    }
    __syncthreads();

    // Warp-prefix compaction offsets; early out if nothing kept.
    unsigned m0 = s_mask[0], m1 = s_mask[1], m2 = s_mask[2], m3 = s_mask[3];
    int base1 = __popc(m0);
    int base2 = base1 + __popc(m1);
    int base3 = base2 + __popc(m2);
    int K = base3 + __popc(m3);
    if (K == 0) return;

    if (t < HN && kept) {
        int lane = t & 31;
        unsigned mm = s_mask[wu];
        int basew = (wu == 0) ? 0 : (wu == 1) ? base1 : (wu == 2) ? base2 : base3;
        int pos = basew + __popc(mm & ((1u << lane) - 1u));
        s_lcell[pos] = cellv;
        s_loff[pos] = xoffv;
    }
    __syncthreads();

    int ref = s_lcell[0];
    int ok = (t < HN) ? ((s_cell[t] < 0) | (s_cell[t] == ref)) : 1;
    int alleq = __syncthreads_and(ok);

    if (alleq) {
        // Fast path: all kept slices share one cell.
        // c4 = float4 channel group (0..15), p = slice group (0..15).
        // Fully unrolled predicated loop: offsets + loads issue batched
        // (MLP up to 7, no per-iteration LDS->LDG dependency).
        int c4 = t & 15;
        int p = t >> 4;
        float4 acc = make_float4(0.f, 0.f, 0.f, 0.f);
        #pragma unroll
        for (int j = 0; j < 7; j++) {
            int kk = p + j * 16;
            if (kk < K) {
                float4 vv = __ldg((const float4*)(x + s_loff[kk]) + c4);
                acc.x += vv.x; acc.y += vv.y; acc.z += vv.z; acc.w += vv.w;
            }
        }
        float* dstp = &s_part[p][c4 * 4];
        dstp[0] = acc.x; dstp[1] = acc.y; dstp[2] = acc.z; dstp[3] = acc.w;
        __syncthreads();
        if (t < Cv) {
            float sum = 0.f;
            #pragma unroll
            for (int p2 = 0; p2 < 16; p2++) sum += s_part[p2][t];
            atomicAdd(out + (size_t)(b * Cv + t) * NYNX + ref, sum);
        }
    } else {
        // Generic fallback: per-slice atomic add (correct for any inputs).
        for (int kk = 0; kk < K; kk++) {
            int off = s_loff[kk];
            int cell = s_lcell[kk];
            if (t < Cv) {
                atomicAdd(out + (size_t)(b * Cv + t) * NYNX + cell,
                          __ldg(x + off + t));
            }
        }
    }
}

extern "C" void kernel_launch(void* const* d_in, const int* in_sizes, int n_in,
                              void* d_out, int out_size) {
    const float* x = (const float*)d_in[0];
    const float* intr = (const float*)d_in[1];
    const float* pose = (const float*)d_in[2];
    float* out = (float*)d_out;

    // 1) zero the output + one-shot matrix setup (block 0)
    int n4 = out_size / 4;                   // 1,179,648 float4
    fp_zero_setup<<<1152, 256>>>((float4*)out, n4, intr, pose);

    // 2) direct scatter: one block per (b, d, w) column, vectorized smem
    //    reduce, flush straight into the final layout
    int blocks = Bv * Dv * Wv;               // 5760
    fp_scatter_direct<<<blocks, 256>>>(x, out);
}

// round 15
// speedup vs baseline: 1.7703x; 1.0287x over previous
#include <cuda_runtime.h>
#include <cuda_bf16.h>
#include <stdint.h>

// Problem constants
#define Bv 2
#define Nv 4
#define Dv 48
#define Hv 28
#define Wv 60
#define Cv 64
#define NXv 192
#define NYv 192
#define NZv 1
#define NYNX (NYv * NXv)
#define FULLM 0xffffffffu
#define HN (Hv * Nv)   // 112 (h,n) slices per (b,d,w) column

// Precomputed per-(b,n) combine = R @ inv(K) and translation (written once
// by the zero/setup kernel, read by every scatter block via __ldg).
__device__ float g_cmd[Bv * Nv][9];
__device__ float g_trd[Bv * Nv][3];

// ---------------------------------------------------------------------------
// Intrinsics inversion + combine = R @ inv(K): element-wise division by det
// matches LU back-substitution bit-for-bit on this matrix structure
// (validated rel_err ~2.4e-7 across R1-R11). Same op order as the reference.
// ---------------------------------------------------------------------------
__device__ __forceinline__ void compute_combine(
    const float* __restrict__ intr, const float* __restrict__ pose,
    int i, float* cm, float* tr) {
    const float* K = intr + i * 9;
    float a00 = K[0], a01 = K[1], a02 = K[2];
    float a10 = K[3], a11 = K[4], a12 = K[5];
    float a20 = K[6], a21 = K[7], a22 = K[8];

    float det = __fadd_rn(
        __fsub_rn(__fmul_rn(a00, __fsub_rn(__fmul_rn(a11, a22), __fmul_rn(a12, a21))),
                  __fmul_rn(a01, __fsub_rn(__fmul_rn(a10, a22), __fmul_rn(a12, a20)))),
        __fmul_rn(a02, __fsub_rn(__fmul_rn(a10, a21), __fmul_rn(a11, a20))));

    float inv[9];
    inv[0] = __fdiv_rn(__fsub_rn(__fmul_rn(a11, a22), __fmul_rn(a12, a21)), det);
    inv[1] = __fdiv_rn(__fsub_rn(__fmul_rn(a02, a21), __fmul_rn(a01, a22)), det);
    inv[2] = __fdiv_rn(__fsub_rn(__fmul_rn(a01, a12), __fmul_rn(a02, a11)), det);
    inv[3] = __fdiv_rn(__fsub_rn(__fmul_rn(a12, a20), __fmul_rn(a10, a22)), det);
    inv[4] = __fdiv_rn(__fsub_rn(__fmul_rn(a00, a22), __fmul_rn(a02, a20)), det);
    inv[5] = __fdiv_rn(__fsub_rn(__fmul_rn(a02, a10), __fmul_rn(a00, a12)), det);
    inv[6] = __fdiv_rn(__fsub_rn(__fmul_rn(a10, a21), __fmul_rn(a11, a20)), det);
    inv[7] = __fdiv_rn(__fsub_rn(__fmul_rn(a01, a20), __fmul_rn(a00, a21)), det);
    inv[8] = __fdiv_rn(__fsub_rn(__fmul_rn(a00, a11), __fmul_rn(a01, a10)), det);

    const float* P = pose + i * 16;
    #pragma unroll
    for (int r = 0; r < 3; r++) {
        float r0 = P[r * 4 + 0], r1 = P[r * 4 + 1], r2 = P[r * 4 + 2];
        #pragma unroll
        for (int c = 0; c < 3; c++) {
            cm[r * 3 + c] = __fadd_rn(
                __fadd_rn(__fmul_rn(r0, inv[0 * 3 + c]),
                          __fmul_rn(r1, inv[1 * 3 + c])),
                __fmul_rn(r2, inv[2 * 3 + c]));
        }
    }
    tr[0] = P[3];
    tr[1] = P[7];
    tr[2] = P[11];
}

// ---------------------------------------------------------------------------
// Zero the output (harness poisons it to 0xAA) AND hoist the matrix setup:
// block 0 computes the 8 combine matrices ONCE into device globals.
// ---------------------------------------------------------------------------
__global__ __launch_bounds__(256) void fp_zero_setup(
    float4* __restrict__ out4, int n4,
    const float* __restrict__ intr, const float* __restrict__ pose) {
    if (blockIdx.x == 0 && threadIdx.x < Bv * Nv) {
        int i = threadIdx.x;
        compute_combine(intr, pose, i, g_cmd[i], g_trd[i]);
    }
    int idx = blockIdx.x * 256 + threadIdx.x;
    int stride = gridDim.x * 256;
    const float4 z = make_float4(0.f, 0.f, 0.f, 0.f);
    #pragma unroll 4
    for (int i = idx; i < n4; i += stride) out4[i] = z;
}

// ---------------------------------------------------------------------------
// Direct scatter: one block = one (b, d, w) column = 112 (h,n) slices of 64
// channels, all targeting ONE BEV cell (verified at runtime; generic
// fallback preserved).
// R12 prologue cuts: du/dv are compile-time RN constants (no fdiv chains);
// combine matrices read directly via __ldg (broadcast, no smem copy, no
// first barrier); reduce tail halved with a shfl_xor(16) pre-merge.
// ---------------------------------------------------------------------------
__global__ __launch_bounds__(256, 8) void fp_scatter_direct(
    const float* __restrict__ x,
    float* __restrict__ out) {
    __shared__ int s_cell[HN];      // bev index (gy*NX+gx) or -1, per (h,n)
    __shared__ int s_lcell[HN];     // compacted kept cells
    __shared__ int s_loff[HN];      // compacted kept x offsets
    __shared__ unsigned s_mask[4];  // per-warp kept ballots (warps 0-3)
    __shared__ float s_part[8][Cv]; // partial sums (8 warp-merged groups)

    int t = threadIdx.x;
    int blk = blockIdx.x;
    int w = blk % Wv;
    int t1 = blk / Wv;
    int d = t1 % Dv;
    int b = t1 / Dv;

    // Geometry for the 112 (h,n) slices (threads 0..111).
    bool kept = false;
    int cellv = -1, xoffv = 0;
    if (t < HN) {
        int n = t & 3;
        int h = t >> 2;

        // Frustum point. du/dv: IEEE-RN compile-time folds, bit-identical
        // to __fdiv_rn(479,59) / __fdiv_rn(223,27).
        const float du = 479.0f / 59.0f;
        const float dv = 223.0f / 27.0f;
        float u = (w == Wv - 1) ? (float)(Wv * 8 - 1) : __fmul_rn((float)w, du);
        float v = (h == Hv - 1) ? (float)(Hv * 8 - 1) : __fmul_rn((float)h, dv);
        float dd = __fadd_rn(2.0f, (float)d);
        float ud = __fmul_rn(u, dd);
        float vd = __fmul_rn(v, dd);

        const float* cm = g_cmd[b * Nv + n];   // __ldg broadcast (4 addrs/warp)
        const float* tr = g_trd[b * Nv + n];
        float c0 = __ldg(cm + 0), c1 = __ldg(cm + 1), c2 = __ldg(cm + 2);
        float c3 = __ldg(cm + 3), c4_ = __ldg(cm + 4), c5 = __ldg(cm + 5);
        float c6 = __ldg(cm + 6), c7 = __ldg(cm + 7), c8_ = __ldg(cm + 8);
        float t0 = __ldg(tr + 0), t1v = __ldg(tr + 1), t2 = __ldg(tr + 2);

        float g0 = __fadd_rn(
            __fadd_rn(__fadd_rn(__fmul_rn(c0, ud), __fmul_rn(c1, vd)),
                      __fmul_rn(c2, dd)),
            t0);
        float g1 = __fadd_rn(
            __fadd_rn(__fadd_rn(__fmul_rn(c3, ud), __fmul_rn(c4_, vd)),
                      __fmul_rn(c5, dd)),
            t1v);
        float g2 = __fadd_rn(
            __fadd_rn(__fadd_rn(__fmul_rn(c6, ud), __fmul_rn(c7, vd)),
                      __fmul_rn(c8_, dd)),
            t2);
        int gx = (int)__fadd_rn(__fmul_rn(g0, 4.0f), 96.0f);
        int gy = (int)__fadd_rn(__fmul_rn(g1, 4.0f), 96.0f);
        int gz = (int)__fdiv_rn(__fadd_rn(g2, 10.0f), 20.0f);
        kept = (gx >= 0) & (gx < NXv) & (gy >= 0) & (gy < NYv) &
               (gz >= 0) & (gz < NZv);
        cellv = kept ? (gy * NXv + gx) : -1;
        xoffv = ((((b * Nv + n) * Dv + d) * Hv + h) * Wv + w) * Cv;
        s_cell[t] = cellv;
    }
    int wu = t >> 5;
    if (wu < 4) {
        unsigned m = __ballot_sync(FULLM, kept);
        if ((t & 31) == 0) s_mask[wu] = m;
    }
    __syncthreads();

    // Warp-prefix compaction offsets; early out if nothing kept.
    unsigned m0 = s_mask[0], m1 = s_mask[1], m2 = s_mask[2], m3 = s_mask[3];
    int base1 = __popc(m0);
    int base2 = base1 + __popc(m1);
    int base3 = base2 + __popc(m2);
    int K = base3 + __popc(m3);
    if (K == 0) return;

    if (t < HN && kept) {
        int lane = t & 31;
        unsigned mm = s_mask[wu];
        int basew = (wu == 0) ? 0 : (wu == 1) ? base1 : (wu == 2) ? base2 : base3;
        int pos = basew + __popc(mm & ((1u << lane) - 1u));
        s_lcell[pos] = cellv;
        s_loff[pos] = xoffv;
    }
    __syncthreads();

    int ref = s_lcell[0];
    int ok = (t < HN) ? ((s_cell[t] < 0) | (s_cell[t] == ref)) : 1;
    int alleq = __syncthreads_and(ok);

    if (alleq) {
        // Fast path: all kept slices share one cell.
        // c4 = float4 channel group (0..15), p = slice group (0..15).
        // Fully unrolled predicated loop: loads issue batched (MLP up to 7).
        int c4 = t & 15;
        int p = t >> 4;
        float4 acc = make_float4(0.f, 0.f, 0.f, 0.f);
        #pragma unroll
        for (int j = 0; j < 7; j++) {
            int kk = p + j * 16;
            if (kk < K) {
                float4 vv = __ldg((const float4*)(x + s_loff[kk]) + c4);
                acc.x += vv.x; acc.y += vv.y; acc.z += vv.z; acc.w += vv.w;
            }
        }
        // Warp pre-merge: the two p-groups of a warp differ only in bit 4
        // of the lane id -> shfl_xor(16) combines them (16 partials -> 8).
        acc.x += __shfl_xor_sync(FULLM, acc.x, 16);
        acc.y += __shfl_xor_sync(FULLM, acc.y, 16);
        acc.z += __shfl_xor_sync(FULLM, acc.z, 16);
        acc.w += __shfl_xor_sync(FULLM, acc.w, 16);
        if ((t & 31) < 16) {
            float* dstp = &s_part[wu * 2 + 0][c4 * 4];  // warp-group slot
            // note: wu*2+0 collapses the p-pair; index by warp id instead
        }
        if ((t & 31) < 16) {
            float* dstp = &s_part[t >> 5][c4 * 4];
            dstp[0] = acc.x; dstp[1] = acc.y; dstp[2] = acc.z; dstp[3] = acc.w;
        }
        __syncthreads();
        if (t < Cv) {
            float sum = 0.f;
            #pragma unroll
            for (int p2 = 0; p2 < 8; p2++) sum += s_part[p2][t];
            atomicAdd(out + (size_t)(b * Cv + t) * NYNX + ref, sum);
        }
    } else {
        // Generic fallback: per-slice atomic add (correct for any inputs).
        for (int kk = 0; kk < K; kk++) {
            int off = s_loff[kk];
            int cell = s_lcell[kk];
            if (t < Cv) {
                atomicAdd(out + (size_t)(b * Cv + t) * NYNX + cell,
                          __ldg(x + off + t));
            }
        }
    }
}

extern "C" void kernel_launch(void* const* d_in, const int* in_sizes, int n_in,
                              void* d_out, int out_size) {
    const float* x = (const float*)d_in[0];
    const float* intr = (const float*)d_in[1];
    const float* pose = (const float*)d_in[2];
    float* out = (float*)d_out;

    // 1) zero the output + one-shot matrix setup (block 0)
    int n4 = out_size / 4;                   // 1,179,648 float4
    fp_zero_setup<<<1152, 256>>>((float4*)out, n4, intr, pose);

    // 2) direct scatter: one block per (b, d, w) column
    int blocks = Bv * Dv * Wv;               // 5760
    fp_scatter_direct<<<blocks, 256>>>(x, out);
}